// round 14
// baseline (speedup 1.0000x reference)
#include <cuda_runtime.h>
#include <cstdint>

// ---------------------------------------------------------------------------
// GroundingNet  B=16 N=64 E=512
//  L1 (k_main, 784 blocks x 256):
//    [0..15] see/cnt.  q=bid-16: q%4==0 -> zero-stream (192 blocks, DRAM-
//    saturating, concurrent with compute), else compute (576):
//      cc%9==0 -> node (64 blocks, 16 rows fused 512->256->128->64->8)
//      else    -> edge (512 blocks, 2 i's each)
//  L2 (k_fix, 1024 blocks x 128): cnt x cnt corner gather + node_concepts.
// ---------------------------------------------------------------------------

#define DINL __device__ __forceinline__

constexpr int Bb = 16, Nn = 64, Ee = 512;
constexpr int CIMG = 512, H1c = 256, H2c = 128, H3c = 64;
constexpr int ROWS = Bb * Nn;             // 1024
constexpr int NODE_OUT = ROWS * Nn * 8;   // 524288
constexpr int EDGE_OUT4 = ROWS * 64 * 64 * 8 / 4;  // 8388608 float4
constexpr int ZCHUNK = (EDGE_OUT4 + 191) / 192;    // 43691
constexpr int NS = 20;                    // node smem stride (16B-aligned)

__device__ float g_node[ROWS * 8];
__device__ float g_rel[Bb * 64 * 64 * 8];   // 2 MB (L2-resident)
__device__ int   g_see[Bb * 64 * 64];
__device__ int   g_cnt[Bb * 64];

DINL float2 ffma2(float2 a, float2 b, float2 c) {
    float2 d;
    asm("fma.rn.f32x2 %0, %1, %2, %3;"
        : "=l"(reinterpret_cast<unsigned long long&>(d))
        : "l"(reinterpret_cast<unsigned long long&>(a)),
          "l"(reinterpret_cast<unsigned long long&>(b)),
          "l"(reinterpret_cast<unsigned long long&>(c)));
    return d;
}
DINL float sigmoidf_(float x) { return 1.f / (1.f + __expf(-x)); }

// ===========================================================================
// L1
// ===========================================================================
__global__ void __launch_bounds__(256) k_main(
    const int*   __restrict__ edge_index,
    const float* __restrict__ roi,
    const float* __restrict__ w1,  const float* __restrict__ b1,
    const float* __restrict__ bng, const float* __restrict__ bnb,
    const float* __restrict__ bnm, const float* __restrict__ bnv,
    const float* __restrict__ w2,  const float* __restrict__ b2,
    const float* __restrict__ bn2g, const float* __restrict__ bn2b,
    const float* __restrict__ bn2m, const float* __restrict__ bn2v,
    const float* __restrict__ w3,  const float* __restrict__ b3,
    const float* __restrict__ wn,  const float* __restrict__ bnc,
    const float* __restrict__ bbox, const float* __restrict__ dirs,
    const float* __restrict__ prio,
    const float* __restrict__ we1, const float* __restrict__ be1,
    const float* __restrict__ we2, const float* __restrict__ be2,
    const float* __restrict__ wei, const float* __restrict__ bei,
    float* __restrict__ out) {
    __shared__ alignas(16) union {
        struct {                       // edge role: 41 KB
            float ws[64 * 64];
            float e1[64 * 68];         // aliased as e2 [j][c]
            float weis[512];
            float attr[64 * 9];
            float w1B[9 * 64];
            float ai[64], be2s[64], beis[8];
        } e;
        struct {                       // node role: 41 KB (stride 20)
            float xs[64 * NS];         // [k][r], staged per 64-k chunk
            float h1T[256 * NS];
            float h2T[128 * NS];
            float h3T[64 * NS];
        } n;
        struct { int ssrc[512]; int sdst[512]; int srow[4096]; } s;
    } u;
    const int bid = blockIdx.x, t = threadIdx.x;

    if (bid < 16) {
        // ======================= see / cnt build =======================
        const int b = bid;
        const int* ei = edge_index + (size_t)b * 2 * Ee;
        for (int e = t; e < Ee; e += 256) { u.s.ssrc[e] = ei[e]; u.s.sdst[e] = ei[Ee + e]; }
        for (int i = t; i < 4096; i += 256)
            u.s.srow[i] = ((i & 63) == 0) ? (i >> 6) : 0;
        __syncthreads();
        if (t < 64) {
            const int n = t;
            int p = 1;
            #pragma unroll 8
            for (int e = 0; e < Ee; e++) {
                if (u.s.sdst[e] == n) {
                    if (p < 64) u.s.srow[n * 64 + p] = u.s.ssrc[e];
                    p++;
                }
            }
            g_cnt[b * 64 + n] = min(p, 64);
        }
        __syncthreads();
        for (int i = t; i < 1024; i += 256)
            *(int4*)&g_see[b * 4096 + i * 4] = *(const int4*)&u.s.srow[i * 4];
        return;
    }

    const int q = bid - 16;           // 0..767

    if ((q & 3) == 0) {
        // ============= zero-stream: dedicated block, ~700 KB =============
        const int zid = q >> 2;       // 0..191
        const long base = (long)zid * ZCHUNK;
        const int  n = (int)min((long)ZCHUNK, (long)EDGE_OUT4 - base);
        float4* dst = (float4*)(out + NODE_OUT) + base;
        const float4 z4 = make_float4(0.f, 0.f, 0.f, 0.f);
        #pragma unroll 8
        for (int i = t; i < n; i += 256)
            __stcs(&dst[i], z4);
        return;
    }

    const int cc = q - (q >> 2) - 1;  // 0..575

    if (cc % 9 == 0) {
        // ============== node path: 16 rows, 4 fused layers ==============
        const int r0 = (cc / 9) * 16;
        {   // layer1: c = t (256 cols), 16 rows in regs, xs chunked by 64 k
            const int c = t;
            float2 acc[8] = {{0,0},{0,0},{0,0},{0,0},{0,0},{0,0},{0,0},{0,0}};
            for (int kc = 0; kc < CIMG; kc += 64) {
                {
                    const int r = t >> 4, k4 = (t & 15) * 4;
                    float4 v = *(const float4*)&roi[(size_t)(r0 + r) * CIMG + kc + k4];
                    u.n.xs[(k4 + 0) * NS + r] = v.x;
                    u.n.xs[(k4 + 1) * NS + r] = v.y;
                    u.n.xs[(k4 + 2) * NS + r] = v.z;
                    u.n.xs[(k4 + 3) * NS + r] = v.w;
                }
                __syncthreads();
                #pragma unroll 8
                for (int k = 0; k < 64; k++) {
                    const float w = __ldg(&w1[(size_t)(kc + k) * H1c + c]);
                    const float2 wv = make_float2(w, w);
                    const float4 x0 = *(const float4*)&u.n.xs[k * NS];
                    const float4 x1 = *(const float4*)&u.n.xs[k * NS + 4];
                    const float4 x2 = *(const float4*)&u.n.xs[k * NS + 8];
                    const float4 x3 = *(const float4*)&u.n.xs[k * NS + 12];
                    acc[0] = ffma2(make_float2(x0.x, x0.y), wv, acc[0]);
                    acc[1] = ffma2(make_float2(x0.z, x0.w), wv, acc[1]);
                    acc[2] = ffma2(make_float2(x1.x, x1.y), wv, acc[2]);
                    acc[3] = ffma2(make_float2(x1.z, x1.w), wv, acc[3]);
                    acc[4] = ffma2(make_float2(x2.x, x2.y), wv, acc[4]);
                    acc[5] = ffma2(make_float2(x2.z, x2.w), wv, acc[5]);
                    acc[6] = ffma2(make_float2(x3.x, x3.y), wv, acc[6]);
                    acc[7] = ffma2(make_float2(x3.z, x3.w), wv, acc[7]);
                }
                __syncthreads();
            }
            const float s  = bng[c] * rsqrtf(bnv[c] + 1e-5f);
            const float sh = bnb[c] - bnm[c] * s;
            const float bb = b1[c];
            #pragma unroll
            for (int qq = 0; qq < 8; qq++) {
                u.n.h1T[c * NS + qq * 2]     = fmaxf((acc[qq].x + bb) * s + sh, 0.f);
                u.n.h1T[c * NS + qq * 2 + 1] = fmaxf((acc[qq].y + bb) * s + sh, 0.f);
            }
        }
        __syncthreads();
        {   // layer2: cp = t&63 (2 cols), rg = t>>6 (4 rows)
            const int cp = t & 63, rg = t >> 6;
            float2 acc[4] = {{0,0},{0,0},{0,0},{0,0}};
            #pragma unroll 8
            for (int k = 0; k < H1c; k++) {
                const float2 w = *(const float2*)&w2[(size_t)k * H2c + cp * 2];
                const float4 x = *(const float4*)&u.n.h1T[k * NS + rg * 4];
                acc[0] = ffma2(make_float2(x.x, x.x), w, acc[0]);
                acc[1] = ffma2(make_float2(x.y, x.y), w, acc[1]);
                acc[2] = ffma2(make_float2(x.z, x.z), w, acc[2]);
                acc[3] = ffma2(make_float2(x.w, x.w), w, acc[3]);
            }
            const int c = cp * 2;
            const float s0 = bn2g[c]     * rsqrtf(bn2v[c]     + 1e-5f);
            const float s1 = bn2g[c + 1] * rsqrtf(bn2v[c + 1] + 1e-5f);
            const float h0 = bn2b[c]     - bn2m[c]     * s0;
            const float h1v = bn2b[c + 1] - bn2m[c + 1] * s1;
            const float q0 = b2[c], q1 = b2[c + 1];
            #pragma unroll
            for (int qq = 0; qq < 4; qq++) {
                const int r = rg * 4 + qq;
                u.n.h2T[(c    ) * NS + r] = fmaxf((acc[qq].x + q0) * s0 + h0,  0.f);
                u.n.h2T[(c + 1) * NS + r] = fmaxf((acc[qq].y + q1) * s1 + h1v, 0.f);
            }
        }
        __syncthreads();
        {   // layer3: cp = t&31 (2 cols), rg = t>>5 (2 rows)
            const int cp = t & 31, rg = t >> 5;
            float2 acc[2] = {{0,0},{0,0}};
            #pragma unroll 8
            for (int k = 0; k < H2c; k++) {
                const float2 w = *(const float2*)&w3[(size_t)k * H3c + cp * 2];
                const float2 x = *(const float2*)&u.n.h2T[k * NS + rg * 2];
                acc[0] = ffma2(make_float2(x.x, x.x), w, acc[0]);
                acc[1] = ffma2(make_float2(x.y, x.y), w, acc[1]);
            }
            const int c = cp * 2;
            const float q0 = b3[c], q1 = b3[c + 1];
            u.n.h3T[(c    ) * NS + rg * 2    ] = fmaxf(acc[0].x + q0, 0.f);
            u.n.h3T[(c + 1) * NS + rg * 2    ] = fmaxf(acc[0].y + q1, 0.f);
            u.n.h3T[(c    ) * NS + rg * 2 + 1] = fmaxf(acc[1].x + q0, 0.f);
            u.n.h3T[(c + 1) * NS + rg * 2 + 1] = fmaxf(acc[1].y + q1, 0.f);
        }
        __syncthreads();
        if (t < 128) {  // head: 16 r x 8 u
            const int r = t >> 3, uu = t & 7;
            float a = __ldg(&bnc[uu]);
            #pragma unroll 8
            for (int k = 0; k < 64; k++) a += u.n.h3T[k * NS + r] * __ldg(&wn[k * 8 + uu]);
            g_node[(size_t)(r0 + r) * 8 + uu] = sigmoidf_(a);
        }
    } else {
        // ============ edge path: TWO i's of same b per block ============
        const int ib = cc - cc / 9 - 1;     // 0..511
        const int b  = ib >> 5;
        const int i0 = (ib & 31) * 2;
        float* ws  = u.e.ws;
        float* e1s = u.e.e1;
        float* e2s = u.e.e1;   // alias
        for (int i = t; i < 1024; i += 256)
            *(float4*)&ws[i * 4] = *(const float4*)&we2[i * 4];
        for (int i = t; i < 512; i += 256) u.e.weis[i] = wei[i];
        for (int i = t; i < 576; i += 256) {
            const int j = i / 9, d = i - j * 9;
            u.e.attr[i] = (d < 4) ? bbox[(b * 64 + j) * 4 + d] * (1.f / 1024.f)
                        : (d < 8) ? dirs[(b * 64 + j) * 4 + d - 4]
                                  : prio[b * 64 + j];
        }
        for (int i = t; i < 576; i += 256) u.e.w1B[i] = we1[576 + i];
        if (t < 64) u.e.be2s[t] = be2[t];
        if (t < 8)  u.e.beis[t] = bei[t];
        __syncthreads();

        for (int pass = 0; pass < 2; pass++) {
            const int il = i0 + pass, bi = b * 64 + il;
            if (t < 64) {
                float a = be1[t];
                #pragma unroll
                for (int d = 0; d < 9; d++) a += u.e.attr[il * 9 + d] * __ldg(&we1[d * 64 + t]);
                u.e.ai[t] = a;
            }
            __syncthreads();
            {   // e1[k][j] = relu(ai[k] + attr[j] . w1B[.][k])
                const int jj = t & 63, kg = t >> 6, k0 = kg * 16;
                float a[9];
                #pragma unroll
                for (int d = 0; d < 9; d++) a[d] = u.e.attr[jj * 9 + d];
                float acc[16];
                #pragma unroll
                for (int qq = 0; qq < 16; qq++) acc[qq] = 0.f;
                #pragma unroll
                for (int d = 0; d < 9; d++) {
                    #pragma unroll
                    for (int k4 = 0; k4 < 4; k4++) {
                        const float4 w = *(const float4*)&u.e.w1B[d * 64 + k0 + k4 * 4];
                        acc[k4 * 4 + 0] += a[d] * w.x;
                        acc[k4 * 4 + 1] += a[d] * w.y;
                        acc[k4 * 4 + 2] += a[d] * w.z;
                        acc[k4 * 4 + 3] += a[d] * w.w;
                    }
                }
                #pragma unroll
                for (int qq = 0; qq < 16; qq++)
                    e1s[(k0 + qq) * 68 + jj] = fmaxf(u.e.ai[k0 + qq] + acc[qq], 0.f);
            }
            __syncthreads();
            // GEMM1: 64j x 64c, thread tile 4j x 4c
            const int tc = t & 15, tj = t >> 4;
            float2 a01[4] = {{0,0},{0,0},{0,0},{0,0}};
            float2 a23[4] = {{0,0},{0,0},{0,0},{0,0}};
            #pragma unroll 8
            for (int k = 0; k < 64; k++) {
                const float4 a = *(const float4*)&e1s[k * 68 + tj * 4];
                const float4 w = *(const float4*)&ws[k * 64 + tc * 4];
                const float wv[4] = {w.x, w.y, w.z, w.w};
                const float2 r01 = make_float2(a.x, a.y);
                const float2 r23 = make_float2(a.z, a.w);
                #pragma unroll
                for (int ci = 0; ci < 4; ci++) {
                    const float2 wc = make_float2(wv[ci], wv[ci]);
                    a01[ci] = ffma2(r01, wc, a01[ci]);
                    a23[ci] = ffma2(r23, wc, a23[ci]);
                }
            }
            __syncthreads();
            #pragma unroll
            for (int ci = 0; ci < 4; ci++) {
                const int ccx = tc * 4 + ci;
                const float bb = u.e.be2s[ccx];
                e2s[(tj * 4 + 0) * 68 + ccx] = fmaxf(a01[ci].x + bb, 0.f);
                e2s[(tj * 4 + 1) * 68 + ccx] = fmaxf(a01[ci].y + bb, 0.f);
                e2s[(tj * 4 + 2) * 68 + ccx] = fmaxf(a23[ci].x + bb, 0.f);
                e2s[(tj * 4 + 3) * 68 + ccx] = fmaxf(a23[ci].y + bb, 0.f);
            }
            __syncthreads();
            // layer3 + sigmoid
            const int jj = t >> 2, rp = t & 3;
            float2 a3 = make_float2(u.e.beis[rp * 2], u.e.beis[rp * 2 + 1]);
            #pragma unroll 8
            for (int k = 0; k < 64; k++) {
                const float v = e2s[jj * 68 + k];
                const float2 wv = *(const float2*)&u.e.weis[k * 8 + rp * 2];
                a3 = ffma2(make_float2(v, v), wv, a3);
            }
            *(float2*)&g_rel[(((size_t)bi) * 64 + jj) * 8 + rp * 2] =
                make_float2(sigmoidf_(a3.x), sigmoidf_(a3.y));
            __syncthreads();
        }
    }
}

// ===========================================================================
// L2 : corner fixup + node_concepts (small)
// ===========================================================================
__global__ void __launch_bounds__(128) k_fix(float* __restrict__ out) {
    const int bi = blockIdx.x, b = bi >> 6, t = threadIdx.x;
    __shared__ int ssee[64];
    __shared__ int scnt;
    if (t < 64) ssee[t] = g_see[bi * 64 + t];
    if (t == 0) scnt = g_cnt[bi];
    __syncthreads();
    const int cnt = scnt;

    {   // node_concepts row
        const int j = t >> 1, qq = t & 1;
        float4 v = make_float4(0.f, 0.f, 0.f, 0.f);
        if (j < cnt)
            v = *(const float4*)&g_node[((size_t)b * 64 + ssee[j]) * 8 + qq * 4];
        *(float4*)&out[(size_t)bi * 512 + j * 8 + qq * 4] = v;
    }

    const float4* rel4 = (const float4*)g_rel;
    float4* out4 = (float4*)(out + NODE_OUT) + (size_t)bi * 8192;
    const int ty = t >> 3, tx = t & 7;
    for (int j = ty; j < cnt; j += 16) {
        const int sj = ssee[j];
        for (int k = tx; k < cnt; k += 8) {
            const int ro = (b * 4096 + sj * 64 + ssee[k]) * 2;
            const int oo = (j * 64 + k) * 2;
            out4[oo]     = __ldg(&rel4[ro]);
            out4[oo + 1] = __ldg(&rel4[ro + 1]);
        }
    }
}

// ===========================================================================
extern "C" void kernel_launch(void* const* d_in, const int* in_sizes, int n_in,
                              void* d_out, int out_size) {
    const float* roi  = (const float*)d_in[0];
    const float* bbox = (const float*)d_in[1];
    const float* dirs = (const float*)d_in[2];
    const float* prio = (const float*)d_in[3];
    const float* w1   = (const float*)d_in[4];
    const float* b1   = (const float*)d_in[5];
    const float* bn1g = (const float*)d_in[6];
    const float* bn1b = (const float*)d_in[7];
    const float* bn1m = (const float*)d_in[8];
    const float* bn1v = (const float*)d_in[9];
    const float* w2   = (const float*)d_in[10];
    const float* b2   = (const float*)d_in[11];
    const float* bn2g = (const float*)d_in[12];
    const float* bn2b = (const float*)d_in[13];
    const float* bn2m = (const float*)d_in[14];
    const float* bn2v = (const float*)d_in[15];
    const float* w3   = (const float*)d_in[16];
    const float* b3   = (const float*)d_in[17];
    const float* wn   = (const float*)d_in[18];
    const float* bnc  = (const float*)d_in[19];
    const float* we1  = (const float*)d_in[20];
    const float* be1  = (const float*)d_in[21];
    const float* we2  = (const float*)d_in[22];
    const float* be2  = (const float*)d_in[23];
    const float* wei  = (const float*)d_in[24];
    const float* bei  = (const float*)d_in[25];
    const int* edge_index = (const int*)d_in[26];
    float* out = (float*)d_out;

    k_main<<<784, 256>>>(edge_index, roi,
                         w1, b1, bn1g, bn1b, bn1m, bn1v,
                         w2, b2, bn2g, bn2b, bn2m, bn2v,
                         w3, b3, wn, bnc,
                         bbox, dirs, prio,
                         we1, be1, we2, be2, wei, bei, out);
    k_fix<<<1024, 128>>>(out);
}

// round 15
// speedup vs baseline: 1.3257x; 1.3257x over previous
#include <cuda_runtime.h>
#include <cstdint>

// ---------------------------------------------------------------------------
// GroundingNet  B=16 N=64 E=512  (R9 structure restored — empirical optimum)
//  L1 (k_main, 912 blocks x 256):
//    [0..15]   see/cnt build
//    [16..911] interleaved by (q%7): q%7<2 -> ZERO-STREAM (256 blocks,
//              blankets 134MB edge output with zeros, overlaps compute),
//              else compute (640): cc%5==0 node (128), else edge (512, 2 i's)
//  L2 (k_fix, 1024 blocks x 256): corner fixup (cnt x cnt gather from rel,
//              mask==1 there) + node_concepts rows.
// ---------------------------------------------------------------------------

#define DINL __device__ __forceinline__

constexpr int Bb = 16, Nn = 64, Ee = 512;
constexpr int CIMG = 512, H1c = 256, H2c = 128, H3c = 64;
constexpr int ROWS = Bb * Nn;             // 1024
constexpr int NODE_OUT = ROWS * Nn * 8;   // 524288

__device__ float g_node[ROWS * 8];
__device__ float g_rel[Bb * 64 * 64 * 8];   // 2 MB (L2-resident)
__device__ int   g_see[Bb * 64 * 64];
__device__ int   g_cnt[Bb * 64];

DINL float2 ffma2(float2 a, float2 b, float2 c) {
    float2 d;
    asm("fma.rn.f32x2 %0, %1, %2, %3;"
        : "=l"(reinterpret_cast<unsigned long long&>(d))
        : "l"(reinterpret_cast<unsigned long long&>(a)),
          "l"(reinterpret_cast<unsigned long long&>(b)),
          "l"(reinterpret_cast<unsigned long long&>(c)));
    return d;
}
DINL float sigmoidf_(float x) { return 1.f / (1.f + __expf(-x)); }

// ===========================================================================
// L1 : compute + zero-stream
// ===========================================================================
__global__ void __launch_bounds__(256) k_main(
    const int*   __restrict__ edge_index,
    const float* __restrict__ roi,
    const float* __restrict__ w1,  const float* __restrict__ b1,
    const float* __restrict__ bng, const float* __restrict__ bnb,
    const float* __restrict__ bnm, const float* __restrict__ bnv,
    const float* __restrict__ w2,  const float* __restrict__ b2,
    const float* __restrict__ bn2g, const float* __restrict__ bn2b,
    const float* __restrict__ bn2m, const float* __restrict__ bn2v,
    const float* __restrict__ w3,  const float* __restrict__ b3,
    const float* __restrict__ wn,  const float* __restrict__ bnc,
    const float* __restrict__ bbox, const float* __restrict__ dirs,
    const float* __restrict__ prio,
    const float* __restrict__ we1, const float* __restrict__ be1,
    const float* __restrict__ we2, const float* __restrict__ be2,
    const float* __restrict__ wei, const float* __restrict__ bei,
    float* __restrict__ out) {
    __shared__ alignas(16) union {
        struct {                       // edge role: 41 KB
            float ws[64 * 64];
            float e1[64 * 68];         // aliased as e2 [j][c]
            float weis[512];
            float attr[64 * 9];
            float w1B[9 * 64];
            float ai[64], be2s[64], beis[8];
        } e;
        struct {                       // node role: 30.7 KB
            float xs[512 * 8];
            float h1T[256 * 8];
            float h2T[128 * 8];
            float h3T[64 * 8];
        } n;
        struct { int ssrc[512]; int sdst[512]; int srow[4096]; } s;
    } u;
    const int bid = blockIdx.x, t = threadIdx.x;

    if (bid < 16) {
        // ======================= see / cnt build =======================
        const int b = bid;
        const int* ei = edge_index + (size_t)b * 2 * Ee;
        for (int e = t; e < Ee; e += 256) { u.s.ssrc[e] = ei[e]; u.s.sdst[e] = ei[Ee + e]; }
        for (int i = t; i < 4096; i += 256)
            u.s.srow[i] = ((i & 63) == 0) ? (i >> 6) : 0;
        __syncthreads();
        if (t < 64) {
            const int n = t;
            int p = 1;
            #pragma unroll 8
            for (int e = 0; e < Ee; e++) {
                if (u.s.sdst[e] == n) {
                    if (p < 64) u.s.srow[n * 64 + p] = u.s.ssrc[e];
                    p++;
                }
            }
            g_cnt[b * 64 + n] = min(p, 64);
        }
        __syncthreads();
        for (int i = t; i < 1024; i += 256)
            *(int4*)&g_see[b * 4096 + i * 4] = *(const int4*)&u.s.srow[i * 4];
        return;
    }

    const int q = bid - 16;           // 0..895
    const int g = q / 7, r = q % 7;

    if (r < 2) {
        // ================== zero-stream: 524 KB per block ==================
        const int zid = g * 2 + r;    // 0..255
        float4* dst = (float4*)(out + NODE_OUT) + (size_t)zid * 32768;
        const float4 z4 = make_float4(0.f, 0.f, 0.f, 0.f);
        #pragma unroll 8
        for (int i = t; i < 32768; i += 256)
            __stcs(&dst[i], z4);
        return;
    }

    const int cc = g * 5 + (r - 2);   // 0..639

    if (cc % 5 == 0) {
        // ============== node path: 8 rows, 4 fused layers ==============
        const int r0 = (cc / 5) * 8;
        for (int i = t; i < 1024; i += 256) {
            const int rr = i >> 7, kq = (i & 127) << 2;
            float4 v = *(const float4*)&roi[(size_t)(r0 + rr) * CIMG + kq];
            u.n.xs[(kq + 0) * 8 + rr] = v.x;
            u.n.xs[(kq + 1) * 8 + rr] = v.y;
            u.n.xs[(kq + 2) * 8 + rr] = v.z;
            u.n.xs[(kq + 3) * 8 + rr] = v.w;
        }
        __syncthreads();
        {   // layer1: c = t
            const int c = t;
            float2 acc[4] = {{0,0},{0,0},{0,0},{0,0}};
            #pragma unroll 8
            for (int k = 0; k < CIMG; k++) {
                const float w = __ldg(&w1[(size_t)k * H1c + c]);
                const float2 wv = make_float2(w, w);
                const float4 x0 = *(const float4*)&u.n.xs[k * 8];
                const float4 x1 = *(const float4*)&u.n.xs[k * 8 + 4];
                acc[0] = ffma2(make_float2(x0.x, x0.y), wv, acc[0]);
                acc[1] = ffma2(make_float2(x0.z, x0.w), wv, acc[1]);
                acc[2] = ffma2(make_float2(x1.x, x1.y), wv, acc[2]);
                acc[3] = ffma2(make_float2(x1.z, x1.w), wv, acc[3]);
            }
            const float s  = bng[c] * rsqrtf(bnv[c] + 1e-5f);
            const float sh = bnb[c] - bnm[c] * s;
            const float bb = b1[c];
            #pragma unroll
            for (int qq = 0; qq < 4; qq++) {
                u.n.h1T[c * 8 + qq * 2]     = fmaxf((acc[qq].x + bb) * s + sh, 0.f);
                u.n.h1T[c * 8 + qq * 2 + 1] = fmaxf((acc[qq].y + bb) * s + sh, 0.f);
            }
        }
        __syncthreads();
        {   // layer2
            const int c = t & 127, rg = t >> 7;
            float2 acc[2] = {{0,0},{0,0}};
            #pragma unroll 8
            for (int k = 0; k < H1c; k++) {
                const float w = __ldg(&w2[(size_t)k * H2c + c]);
                const float2 wv = make_float2(w, w);
                const float4 x = *(const float4*)&u.n.h1T[k * 8 + rg * 4];
                acc[0] = ffma2(make_float2(x.x, x.y), wv, acc[0]);
                acc[1] = ffma2(make_float2(x.z, x.w), wv, acc[1]);
            }
            const float s  = bn2g[c] * rsqrtf(bn2v[c] + 1e-5f);
            const float sh = bn2b[c] - bn2m[c] * s;
            const float bb = b2[c];
            u.n.h2T[c * 8 + rg * 4 + 0] = fmaxf((acc[0].x + bb) * s + sh, 0.f);
            u.n.h2T[c * 8 + rg * 4 + 1] = fmaxf((acc[0].y + bb) * s + sh, 0.f);
            u.n.h2T[c * 8 + rg * 4 + 2] = fmaxf((acc[1].x + bb) * s + sh, 0.f);
            u.n.h2T[c * 8 + rg * 4 + 3] = fmaxf((acc[1].y + bb) * s + sh, 0.f);
        }
        __syncthreads();
        {   // layer3
            const int c = t & 63, rg = t >> 6;
            float2 acc = {0.f, 0.f};
            #pragma unroll 8
            for (int k = 0; k < H2c; k++) {
                const float w = __ldg(&w3[(size_t)k * H3c + c]);
                const float2 x = *(const float2*)&u.n.h2T[k * 8 + rg * 2];
                acc = ffma2(x, make_float2(w, w), acc);
            }
            const float bb = b3[c];
            u.n.h3T[c * 8 + rg * 2    ] = fmaxf(acc.x + bb, 0.f);
            u.n.h3T[c * 8 + rg * 2 + 1] = fmaxf(acc.y + bb, 0.f);
        }
        __syncthreads();
        if (t < 64) {   // head
            const int rr = t >> 3, uu = t & 7;
            float a = __ldg(&bnc[uu]);
            #pragma unroll 8
            for (int k = 0; k < 64; k++) a += u.n.h3T[k * 8 + rr] * __ldg(&wn[k * 8 + uu]);
            g_node[(size_t)(r0 + rr) * 8 + uu] = sigmoidf_(a);
        }
    } else {
        // ============ edge path: TWO i's of same b per block ============
        const int ib = cc - cc / 5 - 1;     // 0..511
        const int b  = ib >> 5;
        const int i0 = (ib & 31) * 2;
        float* ws  = u.e.ws;
        float* e1s = u.e.e1;
        float* e2s = u.e.e1;   // alias
        for (int i = t; i < 1024; i += 256)
            *(float4*)&ws[i * 4] = *(const float4*)&we2[i * 4];
        for (int i = t; i < 512; i += 256) u.e.weis[i] = wei[i];
        for (int i = t; i < 576; i += 256) {
            const int j = i / 9, d = i - j * 9;
            u.e.attr[i] = (d < 4) ? bbox[(b * 64 + j) * 4 + d] * (1.f / 1024.f)
                        : (d < 8) ? dirs[(b * 64 + j) * 4 + d - 4]
                                  : prio[b * 64 + j];
        }
        for (int i = t; i < 576; i += 256) u.e.w1B[i] = we1[576 + i];
        if (t < 64) u.e.be2s[t] = be2[t];
        if (t < 8)  u.e.beis[t] = bei[t];
        __syncthreads();

        for (int pass = 0; pass < 2; pass++) {
            const int il = i0 + pass, bi = b * 64 + il;
            if (t < 64) {
                float a = be1[t];
                #pragma unroll
                for (int d = 0; d < 9; d++) a += u.e.attr[il * 9 + d] * __ldg(&we1[d * 64 + t]);
                u.e.ai[t] = a;
            }
            __syncthreads();
            {   // e1[k][j] = relu(ai[k] + attr[j] . w1B[.][k])
                const int jj = t & 63, kg = t >> 6, k0 = kg * 16;
                float a[9];
                #pragma unroll
                for (int d = 0; d < 9; d++) a[d] = u.e.attr[jj * 9 + d];
                float acc[16];
                #pragma unroll
                for (int qq = 0; qq < 16; qq++) acc[qq] = 0.f;
                #pragma unroll
                for (int d = 0; d < 9; d++) {
                    #pragma unroll
                    for (int k4 = 0; k4 < 4; k4++) {
                        const float4 w = *(const float4*)&u.e.w1B[d * 64 + k0 + k4 * 4];
                        acc[k4 * 4 + 0] += a[d] * w.x;
                        acc[k4 * 4 + 1] += a[d] * w.y;
                        acc[k4 * 4 + 2] += a[d] * w.z;
                        acc[k4 * 4 + 3] += a[d] * w.w;
                    }
                }
                #pragma unroll
                for (int qq = 0; qq < 16; qq++)
                    e1s[(k0 + qq) * 68 + jj] = fmaxf(u.e.ai[k0 + qq] + acc[qq], 0.f);
            }
            __syncthreads();
            // GEMM1: 64j x 64c, thread tile 4j x 4c
            const int tc = t & 15, tj = t >> 4;
            float2 a01[4] = {{0,0},{0,0},{0,0},{0,0}};
            float2 a23[4] = {{0,0},{0,0},{0,0},{0,0}};
            #pragma unroll 8
            for (int k = 0; k < 64; k++) {
                const float4 a = *(const float4*)&e1s[k * 68 + tj * 4];
                const float4 w = *(const float4*)&ws[k * 64 + tc * 4];
                const float wv[4] = {w.x, w.y, w.z, w.w};
                const float2 r01 = make_float2(a.x, a.y);
                const float2 r23 = make_float2(a.z, a.w);
                #pragma unroll
                for (int ci = 0; ci < 4; ci++) {
                    const float2 wc = make_float2(wv[ci], wv[ci]);
                    a01[ci] = ffma2(r01, wc, a01[ci]);
                    a23[ci] = ffma2(r23, wc, a23[ci]);
                }
            }
            __syncthreads();
            #pragma unroll
            for (int ci = 0; ci < 4; ci++) {
                const int ccx = tc * 4 + ci;
                const float bb = u.e.be2s[ccx];
                e2s[(tj * 4 + 0) * 68 + ccx] = fmaxf(a01[ci].x + bb, 0.f);
                e2s[(tj * 4 + 1) * 68 + ccx] = fmaxf(a01[ci].y + bb, 0.f);
                e2s[(tj * 4 + 2) * 68 + ccx] = fmaxf(a23[ci].x + bb, 0.f);
                e2s[(tj * 4 + 3) * 68 + ccx] = fmaxf(a23[ci].y + bb, 0.f);
            }
            __syncthreads();
            // layer3 + sigmoid
            const int jj = t >> 2, rp = t & 3;
            float2 a3 = make_float2(u.e.beis[rp * 2], u.e.beis[rp * 2 + 1]);
            #pragma unroll 8
            for (int k = 0; k < 64; k++) {
                const float v = e2s[jj * 68 + k];
                const float2 wv = *(const float2*)&u.e.weis[k * 8 + rp * 2];
                a3 = ffma2(make_float2(v, v), wv, a3);
            }
            *(float2*)&g_rel[(((size_t)bi) * 64 + jj) * 8 + rp * 2] =
                make_float2(sigmoidf_(a3.x), sigmoidf_(a3.y));
            __syncthreads();
        }
    }
}

// ===========================================================================
// L2 : corner fixup + node_concepts (256 threads: more gather parallelism)
// ===========================================================================
__global__ void __launch_bounds__(256) k_fix(float* __restrict__ out) {
    const int bi = blockIdx.x, b = bi >> 6, t = threadIdx.x;
    __shared__ int ssee[64];
    __shared__ int scnt;
    if (t < 64) ssee[t] = g_see[bi * 64 + t];
    if (t == 0) scnt = g_cnt[bi];
    __syncthreads();
    const int cnt = scnt;

    if (t < 128) {  // node_concepts row: 64 j x 8 u (mask applied via zero)
        const int j = t >> 1, qq = t & 1;
        float4 v = make_float4(0.f, 0.f, 0.f, 0.f);
        if (j < cnt)
            v = *(const float4*)&g_node[((size_t)b * 64 + ssee[j]) * 8 + qq * 4];
        *(float4*)&out[(size_t)bi * 512 + j * 8 + qq * 4] = v;
    }

    // corner: j,k < cnt, mask == 1 -> copy rel
    const float4* rel4 = (const float4*)g_rel;
    float4* out4 = (float4*)(out + NODE_OUT) + (size_t)bi * 8192;
    const int ty = t >> 3, tx = t & 7;     // 32 x 8 thread grid
    for (int j = ty; j < cnt; j += 32) {
        const int sj = ssee[j];
        for (int k = tx; k < cnt; k += 8) {
            const int ro = (b * 4096 + sj * 64 + ssee[k]) * 2;
            const int oo = (j * 64 + k) * 2;
            out4[oo]     = __ldg(&rel4[ro]);
            out4[oo + 1] = __ldg(&rel4[ro + 1]);
        }
    }
}

// ===========================================================================
extern "C" void kernel_launch(void* const* d_in, const int* in_sizes, int n_in,
                              void* d_out, int out_size) {
    const float* roi  = (const float*)d_in[0];
    const float* bbox = (const float*)d_in[1];
    const float* dirs = (const float*)d_in[2];
    const float* prio = (const float*)d_in[3];
    const float* w1   = (const float*)d_in[4];
    const float* b1   = (const float*)d_in[5];
    const float* bn1g = (const float*)d_in[6];
    const float* bn1b = (const float*)d_in[7];
    const float* bn1m = (const float*)d_in[8];
    const float* bn1v = (const float*)d_in[9];
    const float* w2   = (const float*)d_in[10];
    const float* b2   = (const float*)d_in[11];
    const float* bn2g = (const float*)d_in[12];
    const float* bn2b = (const float*)d_in[13];
    const float* bn2m = (const float*)d_in[14];
    const float* bn2v = (const float*)d_in[15];
    const float* w3   = (const float*)d_in[16];
    const float* b3   = (const float*)d_in[17];
    const float* wn   = (const float*)d_in[18];
    const float* bnc  = (const float*)d_in[19];
    const float* we1  = (const float*)d_in[20];
    const float* be1  = (const float*)d_in[21];
    const float* we2  = (const float*)d_in[22];
    const float* be2  = (const float*)d_in[23];
    const float* wei  = (const float*)d_in[24];
    const float* bei  = (const float*)d_in[25];
    const int* edge_index = (const int*)d_in[26];
    float* out = (float*)d_out;

    k_main<<<912, 256>>>(edge_index, roi,
                         w1, b1, bn1g, bn1b, bn1m, bn1v,
                         w2, b2, bn2g, bn2b, bn2m, bn2v,
                         w3, b3, wn, bnc,
                         bbox, dirs, prio,
                         we1, be1, we2, be2, wei, bei, out);
    k_fix<<<1024, 256>>>(out);
}